// round 12
// baseline (speedup 1.0000x reference)
#include <cuda_runtime.h>
#include <cuda_bf16.h>
#include <cstdint>
#include <cmath>

// Problem dims (fixed by the reference).
#define TT 512
#define BB 256
#define HH 512
#define G3 1536
#define MTOT (TT*BB)   // 131072

// -------------------- device scratch (no cudaMalloc allowed) --------------------
__device__ uint16_t g_Xh[(size_t)MTOT * HH];        // bf16 hi of ins
__device__ uint16_t g_Xl[(size_t)MTOT * HH];        // bf16 lo of ins
__device__ uint16_t g_Wt_hi[(size_t)G3 * HH];       // input weights, transposed [ncol][k]
__device__ uint16_t g_Wt_lo[(size_t)G3 * HH];
__device__ uint16_t g_Wht_hi[(size_t)G3 * HH];      // hidden weights, transposed [ncol][k]
__device__ uint16_t g_Wht_lo[(size_t)G3 * HH];
__device__ uint16_t g_Hh[2 * BB * HH];              // ping-pong split h (hi)
__device__ uint16_t g_Hl[2 * BB * HH];              // ping-pong split h (lo)
__device__ float    g_bias[G3];                     // [b_ir | b_iz | b_in]
__device__ unsigned int g_bar4[4];                  // per-b-quarter barriers (32 CTAs each)

// -------------------- helpers --------------------
__device__ __forceinline__ uint32_t smem_u32(const void* p) {
    uint32_t a;
    asm("{ .reg .u64 t; cvta.to.shared.u64 t, %1; cvt.u32.u64 %0, t; }" : "=r"(a) : "l"(p));
    return a;
}
__device__ __forceinline__ void ldm_x4(uint32_t* r, uint32_t addr) {
    asm volatile("ldmatrix.sync.aligned.m8n8.x4.shared.b16 {%0,%1,%2,%3}, [%4];"
                 : "=r"(r[0]), "=r"(r[1]), "=r"(r[2]), "=r"(r[3]) : "r"(addr));
}
__device__ __forceinline__ void ldm_x2(uint32_t* r, uint32_t addr) {
    asm volatile("ldmatrix.sync.aligned.m8n8.x2.shared.b16 {%0,%1}, [%2];"
                 : "=r"(r[0]), "=r"(r[1]) : "r"(addr));
}
// D(16x8,f32) += A(16x16 bf16 row) * B(16x8 bf16 col)
__device__ __forceinline__ void mma16816(float* c, const uint32_t* a, const uint32_t* b) {
    asm volatile("mma.sync.aligned.m16n8k16.row.col.f32.bf16.bf16.f32 "
                 "{%0,%1,%2,%3}, {%4,%5,%6,%7}, {%8,%9}, {%0,%1,%2,%3};"
                 : "+f"(c[0]), "+f"(c[1]), "+f"(c[2]), "+f"(c[3])
                 : "r"(a[0]), "r"(a[1]), "r"(a[2]), "r"(a[3]), "r"(b[0]), "r"(b[1]));
}
__device__ __forceinline__ void cp16z(uint32_t dst, const void* src, uint32_t srcsz) {
    asm volatile("cp.async.cg.shared.global [%0], [%1], 16, %2;" :: "r"(dst), "l"(src), "r"(srcsz));
}
#define CP_COMMIT() asm volatile("cp.async.commit_group;" ::: "memory")
#define CP_WAIT0()  asm volatile("cp.async.wait_group 0;" ::: "memory")
__device__ __forceinline__ void split2(float x, uint16_t& h, uint16_t& l) {
    __nv_bfloat16 hb = __float2bfloat16_rn(x);
    __nv_bfloat16 lb = __float2bfloat16_rn(x - __bfloat162float(hb));
    h = __bfloat16_as_ushort(hb);
    l = __bfloat16_as_ushort(lb);
}
__device__ __forceinline__ float sigmoidf_(float x) { return 1.0f / (1.0f + expf(-x)); }

// ----------------------------------------------------------------------------
// Prep 1: split ins fp32 -> bf16 hi/lo, row-major [MTOT][512].
// ----------------------------------------------------------------------------
__global__ __launch_bounds__(256) void prep_x_kernel(const float* __restrict__ X) {
    size_t u = (size_t)blockIdx.x * 256 + threadIdx.x;
    if (u >= (size_t)MTOT * HH / 8) return;
    size_t base = u * 8;
    float4 v0 = *(const float4*)(X + base);
    float4 v1 = *(const float4*)(X + base + 4);
    float xs[8] = {v0.x, v0.y, v0.z, v0.w, v1.x, v1.y, v1.z, v1.w};
    uint16_t hp[8], lp[8];
#pragma unroll
    for (int j = 0; j < 8; ++j) split2(xs[j], hp[j], lp[j]);
    *(uint4*)(g_Xh + base) = *(uint4*)hp;
    *(uint4*)(g_Xl + base) = *(uint4*)lp;
}

// ----------------------------------------------------------------------------
// Prep 2: transpose + split BOTH weight sets: Wt[ncol][k] = W_gate[k][j].
// ----------------------------------------------------------------------------
__global__ __launch_bounds__(256) void prep_w_kernel(
    const float* __restrict__ Wir, const float* __restrict__ Wiz, const float* __restrict__ Win,
    const float* __restrict__ Whr, const float* __restrict__ Whz, const float* __restrict__ Whn,
    const float* __restrict__ bir, const float* __restrict__ biz, const float* __restrict__ bin) {
    int u = blockIdx.x * 256 + threadIdx.x;
    if (u >= G3 * HH / 8) return;
    int ncol = u >> 6;
    int k0 = (u & 63) * 8;
    int gate = ncol >> 9, j = ncol & 511;
    const float* Wi = (gate == 0) ? Wir : (gate == 1) ? Wiz : Win;
    const float* Wh = (gate == 0) ? Whr : (gate == 1) ? Whz : Whn;
    uint16_t ih[8], il[8], hh[8], hl[8];
#pragma unroll
    for (int i = 0; i < 8; ++i) {
        split2(Wi[(size_t)(k0 + i) * HH + j], ih[i], il[i]);
        split2(Wh[(size_t)(k0 + i) * HH + j], hh[i], hl[i]);
    }
    size_t off = (size_t)ncol * HH + k0;
    *(uint4*)(g_Wt_hi + off)  = *(uint4*)ih;
    *(uint4*)(g_Wt_lo + off)  = *(uint4*)il;
    *(uint4*)(g_Wht_hi + off) = *(uint4*)hh;
    *(uint4*)(g_Wht_lo + off) = *(uint4*)hl;
    if ((u & 63) == 0) {
        const float* bias = (gate == 0) ? bir : (gate == 1) ? biz : bin;
        g_bias[ncol] = bias[j];
    }
}

// ----------------------------------------------------------------------------
// Prep 3: split init_h into ping-pong buffer 0 (bf16 hi/lo); reset barriers.
// ----------------------------------------------------------------------------
__global__ __launch_bounds__(256) void prep_h_kernel(const float* __restrict__ H0) {
    int u = blockIdx.x * 256 + threadIdx.x;
    if (u < 4) g_bar4[u] = 0;
    if (u >= BB * HH / 8) return;
    size_t base = (size_t)u * 8;
    float4 v0 = *(const float4*)(H0 + base);
    float4 v1 = *(const float4*)(H0 + base + 4);
    float xs[8] = {v0.x, v0.y, v0.z, v0.w, v1.x, v1.y, v1.z, v1.w};
    uint16_t hp[8], lp[8];
#pragma unroll
    for (int j = 0; j < 8; ++j) split2(xs[j], hp[j], lp[j]);
    *(uint4*)(g_Hh + base) = *(uint4*)hp;
    *(uint4*)(g_Hl + base) = *(uint4*)lp;
}

// ----------------------------------------------------------------------------
// FUSED persistent GRU: per step, computes BOTH the x-projection (x_t @ W_i)
// and the h-GEMM (h @ W_h) on tensor cores, then the GRU epilogue. No g_Xg.
// Grid (32 j x 4 b) = 128 CTAs, 512 thr = 16 warps (4 m x 4 k-sub).
// smem: Wi hi/lo + Wh hi/lo (blocked, 48KB each = 192KB) + 2x16KB A ping-pong.
// 16 k-chunks (8 x + 8 h) per step, 1 sync each, depth-1 cp.async lookahead;
// chunk x0 of step t+1 prefetched before the quarter barrier (x indep of h).
// Accumulators c[8][4]: [0..1]=r(f0,f1) x+h summed, [2..3]=z, [4..5]=xn, [6..7]=hn.
// ----------------------------------------------------------------------------
#define SKB_WIH 0
#define SKB_WIL 49152
#define SKB_WHH 98304
#define SKB_WHL 147456
#define SKB_A   196608
#define SKB_ABUF 16384
#define SKB_TOTAL 229376

__global__ __launch_bounds__(512) void gru_persistent(
    const int* __restrict__ resets, const float* __restrict__ init_h,
    const float* __restrict__ bhn, float* __restrict__ out)
{
    extern __shared__ __align__(16) char sk_sm[];
    const uint32_t smb = smem_u32(sk_sm);
    float* red_buf = (float*)(sk_sm + SKB_A);

    const int tid = threadIdx.x;
    const int w = tid >> 5, l = tid & 31;
    const int wm = w & 3, wq = w >> 2;      // m-warp 0..3, k-sub 0..3
    const int j0 = blockIdx.x * 16;         // 16 j-cols per gate
    const int b0 = blockIdx.y * 64;         // 64 batch rows
    const int g = l >> 2, tq = l & 3;
    unsigned int* const my_bar = &g_bar4[blockIdx.y];

    // Load W slices once: 4 regions (Wi hi/lo, Wh hi/lo), blocked [k/16][48][16].
    for (int u = tid; u < 48 * 64; u += 512) {
        const int row = u >> 6, q = u & 63;
        const int gate = row >> 4;
        const int ncol = gate * 512 + j0 + (row & 15);
        const int k = q * 8;
        const uint32_t doff = (uint32_t)(((k >> 4) * 48 + row) * 32 + (k & 15) * 2);
        *(uint4*)(sk_sm + SKB_WIH + doff) = *(const uint4*)(g_Wt_hi  + (size_t)ncol * HH + k);
        *(uint4*)(sk_sm + SKB_WIL + doff) = *(const uint4*)(g_Wt_lo  + (size_t)ncol * HH + k);
        *(uint4*)(sk_sm + SKB_WHH + doff) = *(const uint4*)(g_Wht_hi + (size_t)ncol * HH + k);
        *(uint4*)(sk_sm + SKB_WHL + doff) = *(const uint4*)(g_Wht_lo + (size_t)ncol * HH + k);
    }

    // Staging map: thread -> (row, 8-k segment) of a 64x64 chunk (1 hi + 1 lo cp16).
    const int srow = tid >> 3;
    const int seg = tid & 7;
    const uint32_t sdoff = (uint32_t)((seg >> 1) * 2048 + srow * 32 + (seg & 1) * 16);
    const int skoff = seg * 8;

    // Per-thread epilogue constants + register h-carry (wq==0 threads).
    float2 bir2[2], biz2[2], bin2[2], bhn2[2], hc[2][2];
#pragma unroll
    for (int f = 0; f < 2; ++f) {
        const int jj = j0 + f * 8 + tq * 2;
        bir2[f] = *(const float2*)&g_bias[jj];
        biz2[f] = *(const float2*)&g_bias[512 + jj];
        bin2[f] = *(const float2*)&g_bias[1024 + jj];
        bhn2[f] = *(const float2*)&bhn[jj];
    }
    if (wq == 0) {
#pragma unroll
        for (int rr = 0; rr < 2; ++rr) {
            const int row = b0 + wm * 16 + g + rr * 8;
#pragma unroll
            for (int f = 0; f < 2; ++f)
                hc[rr][f] = *(const float2*)&init_h[(size_t)row * HH + j0 + f * 8 + tq * 2];
        }
    }

    // Prefetch x chunk 0 of t=0 into buf 0.
    {
        const uint16_t* sx = g_Xh + (size_t)(b0 + srow) * HH + skoff;
        const uint16_t* sl = g_Xl + (size_t)(b0 + srow) * HH + skoff;
        cp16z(smb + SKB_A + sdoff, sx, 16);
        cp16z(smb + SKB_A + sdoff + 8192, sl, 16);
        CP_COMMIT();
    }

    for (int t = 0; t < TT; ++t) {
        const int par = t & 1;
        const uint16_t* Hh = g_Hh + (size_t)par * BB * HH;
        const uint16_t* Hl = g_Hl + (size_t)par * BB * HH;
        const uint16_t* Xh = g_Xh + ((size_t)t * BB + b0) * HH;
        const uint16_t* Xl = g_Xl + ((size_t)t * BB + b0) * HH;
        const int* rst = resets + t * BB;
        const uint32_t hsz = (rst[b0 + srow] != 0) ? 0u : 16u;

        float c[8][4];
#pragma unroll
        for (int i = 0; i < 8; ++i)
#pragma unroll
            for (int q = 0; q < 4; ++q) c[i][q] = 0.0f;

        const uint32_t aoff_l = (uint32_t)(wq * 2048 + (wm * 16 + (l & 15)) * 32 + (l >> 4) * 16);
        const uint32_t woff_l = (uint32_t)((l & 7) * 32 + ((l >> 3) & 1) * 16);

        // ---- phase X: chunks 0..7 (x_t @ W_i) ----
        for (int ic = 0; ic < 8; ++ic) {
            CP_WAIT0();
            __syncthreads();
            {   // issue next: x chunk ic+1, or h chunk 0 at ic==7
                const uint32_t dbase = smb + SKB_A + (uint32_t)((ic + 1) & 1) * SKB_ABUF + sdoff;
                if (ic < 7) {
                    const uint16_t* sx = Xh + (size_t)srow * HH + (ic + 1) * 64 + skoff;
                    const uint16_t* sl = Xl + (size_t)srow * HH + (ic + 1) * 64 + skoff;
                    cp16z(dbase, sx, 16);
                    cp16z(dbase + 8192, sl, 16);
                } else {
                    const uint16_t* sh = Hh + (size_t)(b0 + srow) * HH + skoff;
                    const uint16_t* sl = Hl + (size_t)(b0 + srow) * HH + skoff;
                    cp16z(dbase, sh, hsz);
                    cp16z(dbase + 8192, sl, hsz);
                }
                CP_COMMIT();
            }
            const uint32_t abase = smb + SKB_A + (uint32_t)(ic & 1) * SKB_ABUF;
            uint32_t afh[4], afl[4];
            ldm_x4(afh, abase + aoff_l);
            ldm_x4(afl, abase + aoff_l + 8192);
            const uint32_t wb = (uint32_t)((ic * 4 + wq) * 1536) + woff_l;
#pragma unroll
            for (int ni = 0; ni < 6; ++ni) {
                uint32_t bfh[2], bfl[2];
                ldm_x2(bfh, smb + SKB_WIH + wb + (uint32_t)(ni * 256));
                ldm_x2(bfl, smb + SKB_WIL + wb + (uint32_t)(ni * 256));
                float* acc = (ni < 4) ? c[ni] : c[4 + (ni & 1)];
                mma16816(acc, afh, bfh);
                mma16816(acc, afh, bfl);
                mma16816(acc, afl, bfh);
            }
        }

        // ---- phase H: chunks 0..7 (h @ W_h, reset-masked) ----
        for (int ic = 0; ic < 8; ++ic) {
            CP_WAIT0();
            __syncthreads();
            if (ic < 7) {
                const uint32_t dbase = smb + SKB_A + (uint32_t)((ic + 1) & 1) * SKB_ABUF + sdoff;
                const uint16_t* sh = Hh + (size_t)(b0 + srow) * HH + (ic + 1) * 64 + skoff;
                const uint16_t* sl = Hl + (size_t)(b0 + srow) * HH + (ic + 1) * 64 + skoff;
                cp16z(dbase, sh, hsz);
                cp16z(dbase + 8192, sl, hsz);
                CP_COMMIT();
            }
            const uint32_t abase = smb + SKB_A + (uint32_t)(ic & 1) * SKB_ABUF;
            uint32_t afh[4], afl[4];
            ldm_x4(afh, abase + aoff_l);
            ldm_x4(afl, abase + aoff_l + 8192);
            const uint32_t wb = (uint32_t)((ic * 4 + wq) * 1536) + woff_l;
#pragma unroll
            for (int ni = 0; ni < 6; ++ni) {
                uint32_t bfh[2], bfl[2];
                ldm_x2(bfh, smb + SKB_WHH + wb + (uint32_t)(ni * 256));
                ldm_x2(bfl, smb + SKB_WHL + wb + (uint32_t)(ni * 256));
                float* acc = (ni < 4) ? c[ni] : c[6 + (ni & 1)];
                mma16816(acc, afh, bfh);
                mma16816(acc, afh, bfl);
                mma16816(acc, afl, bfh);
            }
        }
        __syncthreads();   // all MMA smem reads done; A region -> red_buf

        // ---- 4-way k reduction, 2 rounds of 16 floats (fits 24KB region) ----
#pragma unroll
        for (int rd = 0; rd < 2; ++rd) {
            if (wq != 0) {
                float* dst = red_buf + (wq - 1) * 128 + wm * 32 + l;
#pragma unroll
                for (int fi = 0; fi < 4; ++fi)
#pragma unroll
                    for (int q = 0; q < 4; ++q)
                        dst[(fi * 4 + q) * 384] = c[rd * 4 + fi][q];
            }
            __syncthreads();
            if (wq == 0) {
                const float* src = red_buf + wm * 32 + l;
#pragma unroll
                for (int fi = 0; fi < 4; ++fi)
#pragma unroll
                    for (int q = 0; q < 4; ++q) {
                        const float* s = src + (fi * 4 + q) * 384;
                        c[rd * 4 + fi][q] += s[0] + s[128] + s[256];
                    }
            }
            __syncthreads();
        }

        // ---- fused GRU epilogue (wq==0), register h-carry ----
        if (wq == 0) {
            float* outt = out + (size_t)t * BB * HH;
            uint16_t* nHh = g_Hh + (size_t)(par ^ 1) * BB * HH;
            uint16_t* nHl = g_Hl + (size_t)(par ^ 1) * BB * HH;
#pragma unroll
            for (int rr = 0; rr < 2; ++rr) {
                const int row = b0 + wm * 16 + g + rr * 8;
                const bool rz = rst[row] != 0;
#pragma unroll
                for (int f = 0; f < 2; ++f) {
                    const int jj = j0 + f * 8 + tq * 2;
                    float2 hp = hc[rr][f];
                    if (rz) { hp.x = 0.0f; hp.y = 0.0f; }
                    const float r0 = sigmoidf_(c[f][rr * 2 + 0] + bir2[f].x);
                    const float r1 = sigmoidf_(c[f][rr * 2 + 1] + bir2[f].y);
                    const float z0 = sigmoidf_(c[2 + f][rr * 2 + 0] + biz2[f].x);
                    const float z1 = sigmoidf_(c[2 + f][rr * 2 + 1] + biz2[f].y);
                    const float n0 = tanhf(c[4 + f][rr * 2 + 0] + bin2[f].x
                                           + r0 * (c[6 + f][rr * 2 + 0] + bhn2[f].x));
                    const float n1 = tanhf(c[4 + f][rr * 2 + 1] + bin2[f].y
                                           + r1 * (c[6 + f][rr * 2 + 1] + bhn2[f].y));
                    const float h0 = (1.0f - z0) * n0 + z0 * hp.x;
                    const float h1 = (1.0f - z1) * n1 + z1 * hp.y;
                    *(float2*)&outt[(size_t)row * HH + jj] = make_float2(h0, h1);
                    hc[rr][f] = make_float2(h0, h1);
                    uint16_t hh0, hl0, hh1, hl1;
                    split2(h0, hh0, hl0);
                    split2(h1, hh1, hl1);
                    *(uint32_t*)&nHh[(size_t)row * HH + jj] = ((uint32_t)hh1 << 16) | hh0;
                    *(uint32_t*)&nHl[(size_t)row * HH + jj] = ((uint32_t)hl1 << 16) | hl0;
                }
            }
        }

        // ---- prefetch x chunk 0 of t+1 (h-independent; hides under barrier) ----
        if (t + 1 < TT) {
            const uint16_t* sx = g_Xh + ((size_t)(t + 1) * BB + b0 + srow) * HH + skoff;
            const uint16_t* sl = g_Xl + ((size_t)(t + 1) * BB + b0 + srow) * HH + skoff;
            cp16z(smb + SKB_A + sdoff, sx, 16);
            cp16z(smb + SKB_A + sdoff + 8192, sl, 16);
            CP_COMMIT();
        }

        // ---- per-b-quarter barrier (release orders the h/out stores) ----
        __syncthreads();
        if (tid == 0) {
            asm volatile("red.release.gpu.add.u32 [%0], %1;" :: "l"(my_bar), "r"(1u) : "memory");
            const unsigned target = 32u * (unsigned)(t + 1);
            unsigned v;
            do {
                asm volatile("ld.acquire.gpu.u32 %0, [%1];" : "=r"(v) : "l"(my_bar) : "memory");
                if (v >= target) break;
                __nanosleep(32);
            } while (true);
        }
        __syncthreads();
    }
}

// ----------------------------------------------------------------------------
// Launch: 3 prep kernels + ONE fused persistent kernel. No input GEMM, no g_Xg.
// Graph-capturable (kernel launches only), allocation-free.
// ----------------------------------------------------------------------------
extern "C" void kernel_launch(void* const* d_in, const int* in_sizes, int n_in,
                              void* d_out, int out_size)
{
    const float* ins    = (const float*)d_in[0];
    const int*   resets = (const int*)d_in[1];
    const float* init_h = (const float*)d_in[2];
    const float* W_ir   = (const float*)d_in[3];
    const float* W_iz   = (const float*)d_in[4];
    const float* W_in   = (const float*)d_in[5];
    const float* b_ir   = (const float*)d_in[6];
    const float* b_iz   = (const float*)d_in[7];
    const float* b_in   = (const float*)d_in[8];
    const float* W_hr   = (const float*)d_in[9];
    const float* W_hz   = (const float*)d_in[10];
    const float* W_hn   = (const float*)d_in[11];
    const float* b_hn   = (const float*)d_in[12];
    float* out = (float*)d_out;

    cudaFuncSetAttribute(gru_persistent,
                         cudaFuncAttributeMaxDynamicSharedMemorySize, SKB_TOTAL);

    prep_x_kernel<<<(int)(((size_t)MTOT * HH / 8 + 255) / 256), 256>>>(ins);
    prep_w_kernel<<<(G3 * HH / 8 + 255) / 256, 256>>>(W_ir, W_iz, W_in,
                                                      W_hr, W_hz, W_hn,
                                                      b_ir, b_iz, b_in);
    prep_h_kernel<<<(BB * HH / 8 + 255) / 256, 256>>>(init_h);

    gru_persistent<<<dim3(32, 4), 512, SKB_TOTAL>>>(resets, init_h, b_hn, out);
}

// round 13
// speedup vs baseline: 1.8062x; 1.8062x over previous
#include <cuda_runtime.h>
#include <cuda_bf16.h>
#include <cstdint>
#include <cmath>

// Problem dims (fixed by the reference).
#define TT 512
#define BB 256
#define HH 512
#define G3 1536

// -------------------- device scratch (no cudaMalloc allowed) --------------------
// Fragment-major A operands: [t][mt(16)][kb(32)][lane(32)] -> uint4 (regs a0..a3).
__device__ uint4    g_Xfh[(size_t)TT * 16 * 32 * 32];   // 134 MB
__device__ uint4    g_Xfl[(size_t)TT * 16 * 32 * 32];   // 134 MB
__device__ uint4    g_Hfh[2 * 16 * 32 * 32];            // ping-pong h (hi)
__device__ uint4    g_Hfl[2 * 16 * 32 * 32];            // ping-pong h (lo)
__device__ uint16_t g_Wt_hi[(size_t)G3 * HH];           // input W, transposed [ncol][k]
__device__ uint16_t g_Wt_lo[(size_t)G3 * HH];
__device__ uint16_t g_Wht_hi[(size_t)G3 * HH];          // hidden W, transposed [ncol][k]
__device__ uint16_t g_Wht_lo[(size_t)G3 * HH];
__device__ float    g_bias[G3];                         // [b_ir | b_iz | b_in]
__device__ unsigned int g_bar4[4];                      // per-b-quarter barriers

// -------------------- helpers --------------------
__device__ __forceinline__ uint32_t smem_u32(const void* p) {
    uint32_t a;
    asm("{ .reg .u64 t; cvta.to.shared.u64 t, %1; cvt.u32.u64 %0, t; }" : "=r"(a) : "l"(p));
    return a;
}
__device__ __forceinline__ void ldm_x2(uint32_t* r, uint32_t addr) {
    asm volatile("ldmatrix.sync.aligned.m8n8.x2.shared.b16 {%0,%1}, [%2];"
                 : "=r"(r[0]), "=r"(r[1]) : "r"(addr));
}
__device__ __forceinline__ void mma16816(float* c, const uint32_t* a, const uint32_t* b) {
    asm volatile("mma.sync.aligned.m16n8k16.row.col.f32.bf16.bf16.f32 "
                 "{%0,%1,%2,%3}, {%4,%5,%6,%7}, {%8,%9}, {%0,%1,%2,%3};"
                 : "+f"(c[0]), "+f"(c[1]), "+f"(c[2]), "+f"(c[3])
                 : "r"(a[0]), "r"(a[1]), "r"(a[2]), "r"(a[3]), "r"(b[0]), "r"(b[1]));
}
__device__ __forceinline__ void split2(float x, uint16_t& h, uint16_t& l) {
    __nv_bfloat16 hb = __float2bfloat16_rn(x);
    __nv_bfloat16 lb = __float2bfloat16_rn(x - __bfloat162float(hb));
    h = __bfloat16_as_ushort(hb);
    l = __bfloat16_as_ushort(lb);
}
__device__ __forceinline__ float sigmoidf_(float x) { return 1.0f / (1.0f + expf(-x)); }

// ----------------------------------------------------------------------------
// Prep 1: split ins -> bf16 hi/lo in FRAGMENT-MAJOR layout.
// u -> (t, mt, kb, lane). Lane's 4 regs: a0=(r0,k0 pair), a1=(r0+8,k0),
// a2=(r0,k0+8), a3=(r0+8,k0+8); r0=mt*16+(l>>2), k0=kb*16+(l&3)*2.
// ----------------------------------------------------------------------------
__global__ __launch_bounds__(256) void prep_x_kernel(const float* __restrict__ X) {
    size_t u = (size_t)blockIdx.x * 256 + threadIdx.x;
    if (u >= (size_t)TT * 16 * 32 * 32) return;
    const int l  = (int)(u & 31);
    const int kb = (int)((u >> 5) & 31);
    const int mt = (int)((u >> 10) & 15);
    const int t  = (int)(u >> 14);
    const int r0 = mt * 16 + (l >> 2);
    const int k0 = kb * 16 + (l & 3) * 2;
    const float* Xp = X + (size_t)t * BB * HH;
    float v[4][2];
    v[0][0] = Xp[(size_t)r0 * HH + k0];           v[0][1] = Xp[(size_t)r0 * HH + k0 + 1];
    v[1][0] = Xp[(size_t)(r0 + 8) * HH + k0];     v[1][1] = Xp[(size_t)(r0 + 8) * HH + k0 + 1];
    v[2][0] = Xp[(size_t)r0 * HH + k0 + 8];       v[2][1] = Xp[(size_t)r0 * HH + k0 + 9];
    v[3][0] = Xp[(size_t)(r0 + 8) * HH + k0 + 8]; v[3][1] = Xp[(size_t)(r0 + 8) * HH + k0 + 9];
    uint32_t hi[4], lo[4];
#pragma unroll
    for (int q = 0; q < 4; ++q) {
        uint16_t h0, l0, h1, l1;
        split2(v[q][0], h0, l0);
        split2(v[q][1], h1, l1);
        hi[q] = (uint32_t)h0 | ((uint32_t)h1 << 16);
        lo[q] = (uint32_t)l0 | ((uint32_t)l1 << 16);
    }
    g_Xfh[u] = make_uint4(hi[0], hi[1], hi[2], hi[3]);
    g_Xfl[u] = make_uint4(lo[0], lo[1], lo[2], lo[3]);
}

// ----------------------------------------------------------------------------
// Prep 2: transpose + split BOTH weight sets (unchanged, proven).
// ----------------------------------------------------------------------------
__global__ __launch_bounds__(256) void prep_w_kernel(
    const float* __restrict__ Wir, const float* __restrict__ Wiz, const float* __restrict__ Win,
    const float* __restrict__ Whr, const float* __restrict__ Whz, const float* __restrict__ Whn,
    const float* __restrict__ bir, const float* __restrict__ biz, const float* __restrict__ bin) {
    int u = blockIdx.x * 256 + threadIdx.x;
    if (u >= G3 * HH / 8) return;
    int ncol = u >> 6;
    int k0 = (u & 63) * 8;
    int gate = ncol >> 9, j = ncol & 511;
    const float* Wi = (gate == 0) ? Wir : (gate == 1) ? Wiz : Win;
    const float* Wh = (gate == 0) ? Whr : (gate == 1) ? Whz : Whn;
    uint16_t ih[8], il[8], hh[8], hl[8];
#pragma unroll
    for (int i = 0; i < 8; ++i) {
        split2(Wi[(size_t)(k0 + i) * HH + j], ih[i], il[i]);
        split2(Wh[(size_t)(k0 + i) * HH + j], hh[i], hl[i]);
    }
    size_t off = (size_t)ncol * HH + k0;
    *(uint4*)(g_Wt_hi + off)  = *(uint4*)ih;
    *(uint4*)(g_Wt_lo + off)  = *(uint4*)il;
    *(uint4*)(g_Wht_hi + off) = *(uint4*)hh;
    *(uint4*)(g_Wht_lo + off) = *(uint4*)hl;
    if ((u & 63) == 0) {
        const float* bias = (gate == 0) ? bir : (gate == 1) ? biz : bin;
        g_bias[ncol] = bias[j];
    }
}

// ----------------------------------------------------------------------------
// Prep 3: init_h -> fragment-major split buffers (parity 0); reset barriers.
// ----------------------------------------------------------------------------
__global__ __launch_bounds__(256) void prep_h_kernel(const float* __restrict__ H0) {
    int u = blockIdx.x * 256 + threadIdx.x;
    if (u < 4) g_bar4[u] = 0;
    if (u >= 16 * 32 * 32) return;
    const int l  = u & 31;
    const int kb = (u >> 5) & 31;
    const int mt = (u >> 10) & 15;
    const int r0 = mt * 16 + (l >> 2);
    const int k0 = kb * 16 + (l & 3) * 2;
    float v[4][2];
    v[0][0] = H0[(size_t)r0 * HH + k0];           v[0][1] = H0[(size_t)r0 * HH + k0 + 1];
    v[1][0] = H0[(size_t)(r0 + 8) * HH + k0];     v[1][1] = H0[(size_t)(r0 + 8) * HH + k0 + 1];
    v[2][0] = H0[(size_t)r0 * HH + k0 + 8];       v[2][1] = H0[(size_t)r0 * HH + k0 + 9];
    v[3][0] = H0[(size_t)(r0 + 8) * HH + k0 + 8]; v[3][1] = H0[(size_t)(r0 + 8) * HH + k0 + 9];
    uint32_t hi[4], lo[4];
#pragma unroll
    for (int q = 0; q < 4; ++q) {
        uint16_t h0, l0, h1, l1;
        split2(v[q][0], h0, l0);
        split2(v[q][1], h1, l1);
        hi[q] = (uint32_t)h0 | ((uint32_t)h1 << 16);
        lo[q] = (uint32_t)l0 | ((uint32_t)l1 << 16);
    }
    g_Hfh[u] = make_uint4(hi[0], hi[1], hi[2], hi[3]);
    g_Hfl[u] = make_uint4(lo[0], lo[1], lo[2], lo[3]);
}

// ----------------------------------------------------------------------------
// FUSED persistent GRU, fragment-fed (no A smem, no staging syncs):
//  - W (Wi+Wh, hi/lo) resident in 192KB smem, blocked layout (proven R12)
//  - A operands LDG'd directly from fragment-major gmem into mma registers
//  - x-phase of step t+1 runs between barrier-arrive and barrier-wait
//  - epilogue writes h as ONE uint4 fragment store per thread (+ out, fp32)
// Grid (32 j x 4 b) = 128 CTAs, 512 thr = 16 warps (4 m x 4 k-quarters).
// Accumulators c[8][4]: 0..1=r, 2..3=z (x+h summed), 4..5=xn, 6..7=hn.
// ----------------------------------------------------------------------------
#define SKB_WIH 0
#define SKB_WIL 49152
#define SKB_WHH 98304
#define SKB_WHL 147456
#define SKB_RED 196608
#define SKB_TOTAL 221184

__global__ __launch_bounds__(512, 1) void gru_persistent(
    const int* __restrict__ resets, const float* __restrict__ init_h,
    const float* __restrict__ bhn, float* __restrict__ out)
{
    extern __shared__ __align__(16) char sk_sm[];
    const uint32_t smb = smem_u32(sk_sm);
    float* red_buf = (float*)(sk_sm + SKB_RED);

    const int tid = threadIdx.x;
    const int w = tid >> 5, l = tid & 31;
    const int wm = w & 3, wq = w >> 2;      // m-warp 0..3, k-quarter 0..3
    const int j0 = blockIdx.x * 16;
    const int b0 = blockIdx.y * 64;
    const int g = l >> 2, tq = l & 3;
    const int mtg = blockIdx.y * 4 + wm;    // global 16-row tile index
    unsigned int* const my_bar = &g_bar4[blockIdx.y];

    // Load W slices once: 4 regions, blocked [k/16][48][16] (proven layout).
    for (int u = tid; u < 48 * 64; u += 512) {
        const int row = u >> 6, q = u & 63;
        const int gate = row >> 4;
        const int ncol = gate * 512 + j0 + (row & 15);
        const int k = q * 8;
        const uint32_t doff = (uint32_t)(((k >> 4) * 48 + row) * 32 + (k & 15) * 2);
        *(uint4*)(sk_sm + SKB_WIH + doff) = *(const uint4*)(g_Wt_hi  + (size_t)ncol * HH + k);
        *(uint4*)(sk_sm + SKB_WIL + doff) = *(const uint4*)(g_Wt_lo  + (size_t)ncol * HH + k);
        *(uint4*)(sk_sm + SKB_WHH + doff) = *(const uint4*)(g_Wht_hi + (size_t)ncol * HH + k);
        *(uint4*)(sk_sm + SKB_WHL + doff) = *(const uint4*)(g_Wht_lo + (size_t)ncol * HH + k);
    }
    __syncthreads();

    const uint32_t woff_l = (uint32_t)((l & 7) * 32 + ((l >> 3) & 1) * 16);

    // Epilogue constants + register h-carry (wq==0 threads).
    float2 bir2[2], biz2[2], bin2[2], bhn2[2], hc[2][2];
#pragma unroll
    for (int f = 0; f < 2; ++f) {
        const int jj = j0 + f * 8 + tq * 2;
        bir2[f] = *(const float2*)&g_bias[jj];
        biz2[f] = *(const float2*)&g_bias[512 + jj];
        bin2[f] = *(const float2*)&g_bias[1024 + jj];
        bhn2[f] = *(const float2*)&bhn[jj];
    }
    if (wq == 0) {
#pragma unroll
        for (int rr = 0; rr < 2; ++rr) {
            const int row = b0 + wm * 16 + g + rr * 8;
#pragma unroll
            for (int f = 0; f < 2; ++f)
                hc[rr][f] = *(const float2*)&init_h[(size_t)row * HH + j0 + f * 8 + tq * 2];
        }
    }

    // Per-warp reset-flag rows (same rows serve frag masking AND epilogue).
    const int fr0 = b0 + wm * 16 + g;
    bool f0 = resets[fr0] != 0, f1 = resets[fr0 + 8] != 0;

    float c[8][4];

    // x-phase macro: fills c[0..5] with x_t @ W_i partials (own k-quarter).
#define X_PHASE(tx) {                                                              \
    _Pragma("unroll")                                                              \
    for (int i = 0; i < 6; ++i)                                                    \
        _Pragma("unroll")                                                          \
        for (int q = 0; q < 4; ++q) c[i][q] = 0.0f;                                \
    const size_t xb = ((size_t)(tx) * 16 + mtg) * 32;                              \
    uint4 fh = g_Xfh[(xb + wq * 8) * 32 + l];                                      \
    uint4 fl = g_Xfl[(xb + wq * 8) * 32 + l];                                      \
    _Pragma("unroll")                                                              \
    for (int ic = 0; ic < 8; ++ic) {                                               \
        uint4 nfh, nfl;                                                            \
        if (ic < 7) {                                                              \
            nfh = g_Xfh[(xb + wq * 8 + ic + 1) * 32 + l];                          \
            nfl = g_Xfl[(xb + wq * 8 + ic + 1) * 32 + l];                          \
        }                                                                          \
        const uint32_t afh[4] = {fh.x, fh.y, fh.z, fh.w};                          \
        const uint32_t afl[4] = {fl.x, fl.y, fl.z, fl.w};                          \
        const uint32_t wb = (uint32_t)((wq * 8 + ic) * 1536) + woff_l;             \
        _Pragma("unroll")                                                          \
        for (int ni = 0; ni < 6; ++ni) {                                           \
            uint32_t bfh[2], bfl[2];                                               \
            ldm_x2(bfh, smb + SKB_WIH + wb + (uint32_t)(ni * 256));                \
            ldm_x2(bfl, smb + SKB_WIL + wb + (uint32_t)(ni * 256));                \
            float* acc = (ni < 4) ? c[ni] : c[4 + (ni - 4)];                       \
            mma16816(acc, afh, bfh);                                               \
            mma16816(acc, afh, bfl);                                               \
            mma16816(acc, afl, bfh);                                               \
        }                                                                          \
        fh = nfh; fl = nfl;                                                        \
    } }

    X_PHASE(0);   // prologue

    for (int t = 0; t < TT; ++t) {
        const int par = t & 1;
        const int* rst = resets + t * BB;

        // ---- h-phase: h @ W_h into c[0..3] (+) and c[6..7] (fresh) ----
#pragma unroll
        for (int i = 6; i < 8; ++i)
#pragma unroll
            for (int q = 0; q < 4; ++q) c[i][q] = 0.0f;
        {
            const uint32_t mm0 = f0 ? 0u : 0xFFFFFFFFu;
            const uint32_t mm1 = f1 ? 0u : 0xFFFFFFFFu;
            const size_t hb = ((size_t)par * 16 + mtg) * 32;
            uint4 fh = g_Hfh[(hb + wq * 8) * 32 + l];
            uint4 fl = g_Hfl[(hb + wq * 8) * 32 + l];
#pragma unroll
            for (int ic = 0; ic < 8; ++ic) {
                uint4 nfh, nfl;
                if (ic < 7) {
                    nfh = g_Hfh[(hb + wq * 8 + ic + 1) * 32 + l];
                    nfl = g_Hfl[(hb + wq * 8 + ic + 1) * 32 + l];
                }
                const uint32_t afh[4] = {fh.x & mm0, fh.y & mm1, fh.z & mm0, fh.w & mm1};
                const uint32_t afl[4] = {fl.x & mm0, fl.y & mm1, fl.z & mm0, fl.w & mm1};
                const uint32_t wb = (uint32_t)((wq * 8 + ic) * 1536) + woff_l;
#pragma unroll
                for (int ni = 0; ni < 6; ++ni) {
                    uint32_t bfh[2], bfl[2];
                    ldm_x2(bfh, smb + SKB_WHH + wb + (uint32_t)(ni * 256));
                    ldm_x2(bfl, smb + SKB_WHL + wb + (uint32_t)(ni * 256));
                    float* acc = (ni < 4) ? c[ni] : c[6 + (ni - 4)];
                    mma16816(acc, afh, bfh);
                    mma16816(acc, afh, bfl);
                    mma16816(acc, afl, bfh);
                }
                fh = nfh; fl = nfl;
            }
        }
        __syncthreads();

        // ---- 4-way k reduction, 2 rounds of 16 floats (24KB region) ----
#pragma unroll
        for (int rd = 0; rd < 2; ++rd) {
            if (wq != 0) {
                float* dst = red_buf + (wq - 1) * 128 + wm * 32 + l;
#pragma unroll
                for (int fi = 0; fi < 4; ++fi)
#pragma unroll
                    for (int q = 0; q < 4; ++q)
                        dst[(fi * 4 + q) * 384] = c[rd * 4 + fi][q];
            }
            __syncthreads();
            if (wq == 0) {
                const float* src = red_buf + wm * 32 + l;
#pragma unroll
                for (int fi = 0; fi < 4; ++fi)
#pragma unroll
                    for (int q = 0; q < 4; ++q) {
                        const float* s = src + (fi * 4 + q) * 384;
                        c[rd * 4 + fi][q] += s[0] + s[128] + s[256];
                    }
            }
            __syncthreads();
        }

        // ---- fused GRU epilogue (wq==0): out (fp32) + h as ONE frag store ----
        if (wq == 0) {
            float* outt = out + (size_t)t * BB * HH;
            uint4 vh, vl;
            uint32_t* ph = (uint32_t*)&vh;
            uint32_t* pl = (uint32_t*)&vl;
#pragma unroll
            for (int rr = 0; rr < 2; ++rr) {
                const int row = b0 + wm * 16 + g + rr * 8;
                const bool rz = (rr == 0) ? f0 : f1;
#pragma unroll
                for (int f = 0; f < 2; ++f) {
                    const int jj = j0 + f * 8 + tq * 2;
                    float2 hp = hc[rr][f];
                    if (rz) { hp.x = 0.0f; hp.y = 0.0f; }
                    const float r0 = sigmoidf_(c[f][rr * 2 + 0] + bir2[f].x);
                    const float r1 = sigmoidf_(c[f][rr * 2 + 1] + bir2[f].y);
                    const float z0 = sigmoidf_(c[2 + f][rr * 2 + 0] + biz2[f].x);
                    const float z1 = sigmoidf_(c[2 + f][rr * 2 + 1] + biz2[f].y);
                    const float n0 = tanhf(c[4 + f][rr * 2 + 0] + bin2[f].x
                                           + r0 * (c[6 + f][rr * 2 + 0] + bhn2[f].x));
                    const float n1 = tanhf(c[4 + f][rr * 2 + 1] + bin2[f].y
                                           + r1 * (c[6 + f][rr * 2 + 1] + bhn2[f].y));
                    const float h0 = (1.0f - z0) * n0 + z0 * hp.x;
                    const float h1 = (1.0f - z1) * n1 + z1 * hp.y;
                    *(float2*)&outt[(size_t)row * HH + jj] = make_float2(h0, h1);
                    hc[rr][f] = make_float2(h0, h1);
                    uint16_t hh0, hl0, hh1, hl1;
                    split2(h0, hh0, hl0);
                    split2(h1, hh1, hl1);
                    ph[f * 2 + rr] = (uint32_t)hh0 | ((uint32_t)hh1 << 16);
                    pl[f * 2 + rr] = (uint32_t)hl0 | ((uint32_t)hl1 << 16);
                }
            }
            const size_t widx = (((size_t)(par ^ 1) * 16 + mtg) * 32 + blockIdx.x) * 32 + l;
            g_Hfh[widx] = vh;
            g_Hfl[widx] = vl;
        }

        if (t + 1 < TT) {
            // arrive ASAP (syncthreads orders all warps' stores before release)
            __syncthreads();
            if (tid == 0)
                asm volatile("red.release.gpu.add.u32 [%0], %1;" :: "l"(my_bar), "r"(1u) : "memory");

            // flags for t+1, then x-phase(t+1) — hides the barrier latency
            f0 = resets[(t + 1) * BB + fr0] != 0;
            f1 = resets[(t + 1) * BB + fr0 + 8] != 0;
            X_PHASE(t + 1);

            if (tid == 0) {
                const unsigned target = 32u * (unsigned)(t + 1);
                unsigned v;
                do {
                    asm volatile("ld.acquire.gpu.u32 %0, [%1];" : "=r"(v) : "l"(my_bar) : "memory");
                    if (v >= target) break;
                    __nanosleep(32);
                } while (true);
            }
            __syncthreads();
        }
    }
#undef X_PHASE
}

// ----------------------------------------------------------------------------
// Launch: 3 prep kernels + ONE fused fragment-fed persistent kernel.
// Graph-capturable (kernel launches only), allocation-free.
// ----------------------------------------------------------------------------
extern "C" void kernel_launch(void* const* d_in, const int* in_sizes, int n_in,
                              void* d_out, int out_size)
{
    const float* ins    = (const float*)d_in[0];
    const int*   resets = (const int*)d_in[1];
    const float* init_h = (const float*)d_in[2];
    const float* W_ir   = (const float*)d_in[3];
    const float* W_iz   = (const float*)d_in[4];
    const float* W_in   = (const float*)d_in[5];
    const float* b_ir   = (const float*)d_in[6];
    const float* b_iz   = (const float*)d_in[7];
    const float* b_in   = (const float*)d_in[8];
    const float* W_hr   = (const float*)d_in[9];
    const float* W_hz   = (const float*)d_in[10];
    const float* W_hn   = (const float*)d_in[11];
    const float* b_hn   = (const float*)d_in[12];
    float* out = (float*)d_out;

    cudaFuncSetAttribute(gru_persistent,
                         cudaFuncAttributeMaxDynamicSharedMemorySize, SKB_TOTAL);

    prep_x_kernel<<<(int)(((size_t)TT * 16 * 32 * 32 + 255) / 256), 256>>>(ins);
    prep_w_kernel<<<(G3 * HH / 8 + 255) / 256, 256>>>(W_ir, W_iz, W_in,
                                                      W_hr, W_hz, W_hn,
                                                      b_ir, b_iz, b_in);
    prep_h_kernel<<<(16 * 32 * 32 + 255) / 256, 256>>>(init_h);

    gru_persistent<<<dim3(32, 4), 512, SKB_TOTAL>>>(resets, init_h, b_hn, out);
}